// round 3
// baseline (speedup 1.0000x reference)
#include <cuda_runtime.h>

#define DD 128
#define NODES_MAX 50000

// Scratch: aggregated neighbor features (allocation-free rule -> __device__ global)
__device__ float g_agg[NODES_MAX * DD];

// ---------------------------------------------------------------------------
// Kernel 1: zero the aggregation buffer
// ---------------------------------------------------------------------------
__global__ void zero_agg_kernel(int n4) {
    float4 z = make_float4(0.f, 0.f, 0.f, 0.f);
    for (int i = blockIdx.x * blockDim.x + threadIdx.x; i < n4;
         i += gridDim.x * blockDim.x) {
        reinterpret_cast<float4*>(g_agg)[i] = z;
    }
}

// ---------------------------------------------------------------------------
// Kernel 2: scatter-add  agg[dst] += x[src]
// One warp per edge; each lane handles one float4 (4 floats) of the 128-wide row.
// Vector float4 atomicAdd (sm_90+) -> 1 RED.128 per lane instead of 4 scalar REDs.
// Indices are int32 (JAX x64-disabled downcasts the reference's int64).
// ---------------------------------------------------------------------------
__global__ __launch_bounds__(256)
void scatter_add_kernel(const float* __restrict__ x,
                        const int* __restrict__ src,
                        const int* __restrict__ dst,
                        int n_edges, int n_nodes) {
    int warp = (blockIdx.x * blockDim.x + threadIdx.x) >> 5;
    int lane = threadIdx.x & 31;
    if (warp >= n_edges) return;

    int s = __ldg(&src[warp]);   // broadcast within warp (1 sector)
    int d = __ldg(&dst[warp]);
    if ((unsigned)s >= (unsigned)n_nodes || (unsigned)d >= (unsigned)n_nodes)
        return;  // fail soft (wrong answer, not a crash) if dtype assumption wrong

    const float4 v = *reinterpret_cast<const float4*>(
        x + (size_t)s * DD + lane * 4);
    atomicAdd(reinterpret_cast<float4*>(g_agg + (size_t)d * DD + lane * 4), v);
}

// ---------------------------------------------------------------------------
// Kernel 3: out = relu(agg @ W^T) + x
// h[i][j] = sum_k agg[i][k] * W[j][k]
// W transposed into smem as Wt[k][j] with pad 132 (528B rows, 16B-aligned,
// conflict-free float4 column reads).
// Each warp processes 4 rows at a time -> Wt smem traffic amortized 4x.
// ---------------------------------------------------------------------------
#define WT_LD 132            // padded leading dim for Wt
#define WARPS_PER_BLOCK 8
#define ROWS_PER_WARP 4

__global__ __launch_bounds__(256)
void gemm_relu_res_kernel(const float* __restrict__ x,
                          const float* __restrict__ W,
                          float* __restrict__ out,
                          int n_rows) {
    extern __shared__ float smem[];
    float* Wt = smem;                              // [128][WT_LD]
    float* rowbuf = smem + DD * WT_LD;             // [WARPS][4][128]

    // Load W transposed.
    for (int idx = threadIdx.x; idx < DD * DD; idx += blockDim.x) {
        int j = idx & (DD - 1);
        int k = idx >> 7;
        Wt[k * WT_LD + j] = W[j * DD + k];
    }
    __syncthreads();

    const int warp = threadIdx.x >> 5;
    const int lane = threadIdx.x & 31;
    float* rb = rowbuf + warp * (ROWS_PER_WARP * DD);

    const int warps_total = gridDim.x * WARPS_PER_BLOCK;
    const int gwarp = blockIdx.x * WARPS_PER_BLOCK + warp;

    for (int r0 = gwarp * ROWS_PER_WARP; r0 < n_rows;
         r0 += warps_total * ROWS_PER_WARP) {

        __syncwarp();
        #pragma unroll
        for (int r = 0; r < ROWS_PER_WARP; r++) {
            int row = r0 + r;
            if (row < n_rows) {
                float4 v = *reinterpret_cast<const float4*>(
                    g_agg + (size_t)row * DD + lane * 4);
                *reinterpret_cast<float4*>(rb + r * DD + lane * 4) = v;
            }
        }
        __syncwarp();

        float4 acc0 = make_float4(0.f, 0.f, 0.f, 0.f);
        float4 acc1 = acc0, acc2 = acc0, acc3 = acc0;

        #pragma unroll 8
        for (int k = 0; k < DD; k += 4) {
            float4 a0 = *reinterpret_cast<const float4*>(rb + 0 * DD + k);
            float4 a1 = *reinterpret_cast<const float4*>(rb + 1 * DD + k);
            float4 a2 = *reinterpret_cast<const float4*>(rb + 2 * DD + k);
            float4 a3 = *reinterpret_cast<const float4*>(rb + 3 * DD + k);
            const float* pa0 = reinterpret_cast<const float*>(&a0);
            const float* pa1 = reinterpret_cast<const float*>(&a1);
            const float* pa2 = reinterpret_cast<const float*>(&a2);
            const float* pa3 = reinterpret_cast<const float*>(&a3);

            #pragma unroll
            for (int kk = 0; kk < 4; kk++) {
                float4 w = *reinterpret_cast<const float4*>(
                    Wt + (k + kk) * WT_LD + lane * 4);
                float b0 = pa0[kk], b1 = pa1[kk], b2 = pa2[kk], b3 = pa3[kk];
                acc0.x += b0 * w.x; acc0.y += b0 * w.y;
                acc0.z += b0 * w.z; acc0.w += b0 * w.w;
                acc1.x += b1 * w.x; acc1.y += b1 * w.y;
                acc1.z += b1 * w.z; acc1.w += b1 * w.w;
                acc2.x += b2 * w.x; acc2.y += b2 * w.y;
                acc2.z += b2 * w.z; acc2.w += b2 * w.w;
                acc3.x += b3 * w.x; acc3.y += b3 * w.y;
                acc3.z += b3 * w.z; acc3.w += b3 * w.w;
            }
        }

        float4 accs[4] = {acc0, acc1, acc2, acc3};
        #pragma unroll
        for (int r = 0; r < ROWS_PER_WARP; r++) {
            int row = r0 + r;
            if (row >= n_rows) break;
            float4 a = accs[r];
            float4 xr = *reinterpret_cast<const float4*>(
                x + (size_t)row * DD + lane * 4);
            float4 res;
            res.x = fmaxf(a.x, 0.f) + xr.x;
            res.y = fmaxf(a.y, 0.f) + xr.y;
            res.z = fmaxf(a.z, 0.f) + xr.z;
            res.w = fmaxf(a.w, 0.f) + xr.w;
            *reinterpret_cast<float4*>(out + (size_t)row * DD + lane * 4) = res;
        }
    }
}

// ---------------------------------------------------------------------------
// Launch
// ---------------------------------------------------------------------------
extern "C" void kernel_launch(void* const* d_in, const int* in_sizes, int n_in,
                              void* d_out, int out_size) {
    const float* x   = (const float*)d_in[0];      // [N, 128] f32
    const float* W   = (const float*)d_in[1];      // [128, 128] f32
    const int*   src = (const int*)d_in[2];        // [E] int32
    const int*   dst = (const int*)d_in[3];        // [E] int32
    float*       out = (float*)d_out;              // [N, 128] f32

    const int n_nodes = in_sizes[0] / DD;
    const int n_edges = in_sizes[2];

    // 1) zero agg
    zero_agg_kernel<<<592, 256>>>(n_nodes * DD / 4);

    // 2) scatter-add (1 warp per edge, 8 edges per 256-thread block)
    int blocks = (n_edges + 7) / 8;
    scatter_add_kernel<<<blocks, 256>>>(x, src, dst, n_edges, n_nodes);

    // 3) fused GEMM + relu + residual
    size_t smem = (DD * WT_LD + WARPS_PER_BLOCK * ROWS_PER_WARP * DD) * sizeof(float);
    cudaFuncSetAttribute(gemm_relu_res_kernel,
                         cudaFuncAttributeMaxDynamicSharedMemorySize, (int)smem);
    gemm_relu_res_kernel<<<296, 256, smem>>>(x, W, out, n_nodes);
}